// round 17
// baseline (speedup 1.0000x reference)
#include <cuda_runtime.h>
#include <cuda_fp16.h>
#include <cstdint>

#define BB   4
#define HH   16
#define SS   2048
#define HD   64
#define DIN  1024
#define DOUT 1024

// ---------------------------------------------------------------------------
// Scratch (__device__ globals; no allocations allowed).  All-fp16 activations.
// ---------------------------------------------------------------------------
__device__ __half g_xh[BB * SS * DIN];       // x fp16
__device__ __half g_wth[4 * DIN * DOUT];     // W^T fp16 [n][k], 4 mats
__device__ __half g_qh[BB * HH * SS * HD];   // Q (pre-scaled) [B,H,S,HD]
__device__ __half g_kh[BB * HH * SS * HD];
__device__ __half g_vh[BB * HH * SS * HD];
__device__ __half g_cxh[BB * SS * DOUT];     // ctx fp16 [8192][1024]

// ---------------------------------------------------------------------------
// Helpers
// ---------------------------------------------------------------------------
__device__ __forceinline__ uint32_t smem_u32(const void* p) {
    uint32_t a;
    asm("{ .reg .u64 t; cvta.to.shared.u64 t, %1; cvt.u32.u64 %0, t; }" : "=r"(a) : "l"(p));
    return a;
}
__device__ __forceinline__ float ex2(float x) {
    float y;
    asm("ex2.approx.f32 %0, %1;" : "=f"(y) : "f"(x));
    return y;
}
__device__ __forceinline__ uint32_t packh2(float a, float b) {
    __half2 t = __floats2half2_rn(a, b);
    return *(uint32_t*)&t;
}
__device__ __forceinline__ void ldsm4(uint32_t& r0, uint32_t& r1, uint32_t& r2, uint32_t& r3,
                                      uint32_t addr) {
    asm volatile("ldmatrix.sync.aligned.m8n8.x4.shared.b16 {%0,%1,%2,%3}, [%4];"
                 : "=r"(r0), "=r"(r1), "=r"(r2), "=r"(r3) : "r"(addr));
}
__device__ __forceinline__ void ldsm4t(uint32_t& r0, uint32_t& r1, uint32_t& r2, uint32_t& r3,
                                       uint32_t addr) {
    asm volatile("ldmatrix.sync.aligned.m8n8.x4.trans.shared.b16 {%0,%1,%2,%3}, [%4];"
                 : "=r"(r0), "=r"(r1), "=r"(r2), "=r"(r3) : "r"(addr));
}
__device__ __forceinline__ void mma16816(float* c, const uint32_t* a, const uint32_t* b) {
    asm volatile(
        "mma.sync.aligned.m16n8k16.row.col.f32.f16.f16.f32 "
        "{%0,%1,%2,%3}, {%4,%5,%6,%7}, {%8,%9}, {%0,%1,%2,%3};"
        : "+f"(c[0]), "+f"(c[1]), "+f"(c[2]), "+f"(c[3])
        : "r"(a[0]), "r"(a[1]), "r"(a[2]), "r"(a[3]), "r"(b[0]), "r"(b[1]));
}
__device__ __forceinline__ void cp16(uint32_t dst, const void* src) {
    asm volatile("cp.async.cg.shared.global [%0], [%1], 16;" :: "r"(dst), "l"(src));
}
__device__ __forceinline__ void cp_commit() { asm volatile("cp.async.commit_group;" ::: "memory"); }
__device__ __forceinline__ void cp_wait1()  { asm volatile("cp.async.wait_group 1;" ::: "memory"); }
__device__ __forceinline__ void cp_wait0()  { asm volatile("cp.async.wait_group 0;" ::: "memory"); }

// ---------------------------------------------------------------------------
// Merged conversion: blocks [0, 8192) convert x -> fp16; [8192, 12288) W^T -> fp16.
// ---------------------------------------------------------------------------
__global__ __launch_bounds__(256) void conv_all_kernel(
    const float* __restrict__ x,
    const float* __restrict__ Wq, const float* __restrict__ Wk,
    const float* __restrict__ Wv, const float* __restrict__ Wo)
{
    __shared__ float t[32][33];
    if (blockIdx.x < 8192) {
        int i = (blockIdx.x * 256 + threadIdx.x) * 4;
        float4 v = *(const float4*)(x + i);
        *(uint2*)&g_xh[i] = make_uint2(packh2(v.x, v.y), packh2(v.z, v.w));
    } else {
        const int w = blockIdx.x - 8192;
        const int z = w >> 10;
        const int b2 = w & 1023;
        const int n0 = (b2 & 31) * 32;
        const int k0 = (b2 >> 5) * 32;
        const float* W = (z == 0) ? Wq : (z == 1) ? Wk : (z == 2) ? Wv : Wo;
        const int tx = threadIdx.x & 31, ty = threadIdx.x >> 5;   // 32 x 8
        #pragma unroll
        for (int i = 0; i < 4; ++i)
            t[ty + i * 8][tx] = W[(size_t)(k0 + ty + i * 8) * DOUT + n0 + tx];
        __syncthreads();
        __half* wh = g_wth + (size_t)z * DIN * DOUT;
        #pragma unroll
        for (int i = 0; i < 4; ++i) {
            int n = n0 + ty + i * 8, k = k0 + tx;
            wh[(size_t)n * DIN + k] = __float2half_rn(t[tx][ty + i * 8]);
        }
    }
}

// ---------------------------------------------------------------------------
// fp16 1-pass GEMM via mma.sync.  CTA 128x128, 256 threads (warp 64x32),
// KC=32, 2 stages, 2 CTAs/SM (4 warps/SMSP).
// MODE 0: A = x, B = W^T[z] -> Q/K/V fp16 (Q pre-scaled).
// MODE 1: A = ctx fp16, B = Wo^T, +bias -> d_out fp32.
// ---------------------------------------------------------------------------
#define KC     32
#define PITCH  80
#define ATILE  (128 * PITCH)             // 10240
#define BTILE  (128 * PITCH)             // 10240
#define STAGEB (ATILE + BTILE)           // 20480
#define GSMEM  (2 * STAGEB)              // 40960

template<int MODE>
__global__ __launch_bounds__(256, 2) void mma_gemm(const float* __restrict__ bias,
                                                   float* __restrict__ dout)
{
    extern __shared__ char smc[];
    const uint32_t smb = smem_u32(smc);

    const int tid  = threadIdx.x;
    const int lane = tid & 31;
    const int wid  = tid >> 5;
    const int wm   = (wid & 1) * 64;
    const int wn   = (wid >> 1) * 32;

    const int m0 = blockIdx.x * 128;
    const int n0 = blockIdx.y * 128;
    const int bz = (MODE == 0) ? blockIdx.z : 3;

    const __half* Ah = (MODE == 0) ? g_xh : g_cxh;
    const __half* Bh = g_wth + (size_t)bz * DIN * DOUT;

    const char* agh = (const char*)Ah + ((size_t)m0 * DIN) * 2;
    const char* bgh = (const char*)Bh + ((size_t)n0 * DIN) * 2;

    auto load = [&](int c, int st) {
        const uint32_t base = smb + st * STAGEB;
        const size_t cko = (size_t)c * KC * 2;
        #pragma unroll
        for (int i = 0; i < 2; ++i) {
            int s   = tid + i * 256;                 // 0..511
            int r   = s >> 2;                        // row 0..127
            int seg = s & 3;
            cp16(base + r * PITCH + seg * 16,
                 agh + (size_t)r * (DIN * 2) + cko + seg * 16);
        }
        #pragma unroll
        for (int i = 0; i < 2; ++i) {
            int s   = tid + i * 256;
            int r   = s >> 2;
            int seg = s & 3;
            cp16(base + ATILE + r * PITCH + seg * 16,
                 bgh + (size_t)r * (DIN * 2) + cko + seg * 16);
        }
    };

    float C[4][4][4] = {};

    const uint32_t aRow = wm + (lane & 15);
    const uint32_t aCol = (lane >> 4) * 16;
    const uint32_t bRow = wn + ((lane >> 4) << 3) + (lane & 7);
    const uint32_t bCol = ((lane >> 3) & 1) * 16;

    load(0, 0);
    cp_commit();

    for (int c = 0; c < DIN / KC; ++c) {
        const int st = c & 1;
        if (c + 1 < DIN / KC) { load(c + 1, st ^ 1); cp_commit(); cp_wait1(); }
        else                  { cp_wait0(); }
        __syncthreads();

        const uint32_t sA = smb + st * STAGEB;
        const uint32_t sB = sA + ATILE;

        #pragma unroll
        for (int ks = 0; ks < 2; ++ks) {
            uint32_t ah[4][4], bh[4][2];
            #pragma unroll
            for (int i = 0; i < 4; ++i) {
                uint32_t ad = sA + (aRow + i * 16) * PITCH + ks * 32 + aCol;
                ldsm4(ah[i][0], ah[i][1], ah[i][2], ah[i][3], ad);
            }
            #pragma unroll
            for (int p = 0; p < 2; ++p) {
                uint32_t bd = sB + (bRow + p * 16) * PITCH + ks * 32 + bCol;
                ldsm4(bh[2*p][0], bh[2*p][1], bh[2*p+1][0], bh[2*p+1][1], bd);
            }
            #pragma unroll
            for (int i = 0; i < 4; ++i)
                #pragma unroll
                for (int j = 0; j < 4; ++j)
                    mma16816(C[i][j], ah[i], bh[j]);
        }
        __syncthreads();
    }

    // ---- epilogue ----
    const int rr = lane >> 2;
    const int cc = (lane & 3) * 2;
    const float scl = (MODE == 0 && bz == 0) ? 0.1803368801111244f : 1.0f; // (1/8)*log2(e)
    #pragma unroll
    for (int i = 0; i < 4; ++i) {
        #pragma unroll
        for (int j = 0; j < 4; ++j) {
            int m1 = m0 + wm + i * 16 + rr;
            int m2 = m1 + 8;
            int n  = n0 + wn + j * 8 + cc;
            if (MODE == 0) {
                __half* oh = (bz == 0) ? g_qh : (bz == 1) ? g_kh : g_vh;
                int head = n >> 6, hd = n & 63;
                #pragma unroll
                for (int half = 0; half < 2; ++half) {
                    int mm = half ? m2 : m1;
                    int b = mm >> 11, s = mm & 2047;
                    size_t idx = (((size_t)(b * HH + head) * SS + s) * HD) + hd;
                    *(uint32_t*)&oh[idx] = packh2(C[i][j][half * 2] * scl,
                                                  C[i][j][half * 2 + 1] * scl);
                }
            } else {
                float b0 = bias[n], b1 = bias[n + 1];
                *(float2*)&dout[(size_t)m1 * DOUT + n] = make_float2(C[i][j][0] + b0, C[i][j][1] + b1);
                *(float2*)&dout[(size_t)m2 * DOUT + n] = make_float2(C[i][j][2] + b0, C[i][j][3] + b1);
            }
        }
    }
}

// ---------------------------------------------------------------------------
// Causal flash attention (fp16, max-free softmax, ex2.approx).
// S = 1-pass (Q*K);  PV = 1-pass (P fp16 * V).  ctx stored fp16.
// CTA: 64 queries x (b,h), 128 threads.  KV tiles of 64, 3 CTAs/SM.
// ---------------------------------------------------------------------------
#define APITCH  144
#define QBYTES  (64 * APITCH)           // 9216
#define KVB     (64 * APITCH)           // 9216
#define OFF_ST  QBYTES
#define STG_B   (2 * KVB)               // 18432 (Kh, Vh)
#define ATTN_SMEM (OFF_ST + 2 * STG_B)  // 46080 -> 3 CTAs/SM

__global__ __launch_bounds__(128, 3) void attn_mma_kernel()
{
    extern __shared__ char smc[];
    const uint32_t smb = smem_u32(smc);

    const int tid  = threadIdx.x;
    const int lane = tid & 31;
    const int wid  = tid >> 5;
    const int qt   = (int)(gridDim.x - 1) - (int)blockIdx.x;  // heavy tiles first
    const int h    = blockIdx.y, b = blockIdx.z;
    const int wq   = wid * 16;

    const size_t bh = ((size_t)(b * HH + h)) * SS;
    const char* gqh = (const char*)(g_qh + (bh + (size_t)qt * 64) * HD);
    const char* gkh = (const char*)(g_kh + bh * HD);
    const char* gvh = (const char*)(g_vh + bh * HD);

    #pragma unroll
    for (int i = 0; i < 4; ++i) {
        int s = tid + i * 128;
        int r = s >> 3, seg = s & 7;
        cp16(smb + r * APITCH + seg * 16, gqh + (size_t)r * 128 + seg * 16);
    }
    auto loadKV = [&](int jt, int st) {
        const uint32_t base = smb + OFF_ST + st * STG_B;
        const size_t g0 = (size_t)jt * 64 * 128;
        #pragma unroll
        for (int i = 0; i < 4; ++i) {
            int s = tid + i * 128;                 // 0..511
            int r = s >> 3, seg = s & 7;
            uint32_t doff = r * APITCH + seg * 16;
            size_t   goff = g0 + (size_t)r * 128 + seg * 16;
            cp16(base + doff,       gkh + goff);
            cp16(base + KVB + doff, gvh + goff);
        }
    };
    loadKV(0, 0);
    cp_commit();

    uint32_t qh[4][4];
    float O[8][4] = {};
    float rs0 = 0.f, rs1 = 0.f;

    const uint32_t aoff = (wq + (lane & 15)) * APITCH + (lane >> 4) * 16;
    const uint32_t krow = (((lane >> 4) << 3) + (lane & 7)) * APITCH + ((lane >> 3) & 1) * 16;
    const uint32_t vrow = (lane & 15) * APITCH + (lane >> 4) * 16;

    for (int jt = 0; jt <= qt; ++jt) {
        const int st = jt & 1;
        if (jt < qt) { loadKV(jt + 1, st ^ 1); cp_commit(); cp_wait1(); }
        else         { cp_wait0(); }
        __syncthreads();

        if (jt == 0) {
            #pragma unroll
            for (int f = 0; f < 4; ++f)
                ldsm4(qh[f][0], qh[f][1], qh[f][2], qh[f][3], smb + aoff + f * 32);
        }

        const uint32_t kb = smb + OFF_ST + st * STG_B;

        // ---- S = Q K^T (1-pass fp16) ----
        float s_[8][4] = {};
        #pragma unroll
        for (int f = 0; f < 4; ++f) {
            uint32_t kh[4][4];
            #pragma unroll
            for (int jp = 0; jp < 4; ++jp) {
                uint32_t a = kb + krow + jp * 16 * APITCH + f * 32;
                ldsm4(kh[jp][0], kh[jp][1], kh[jp][2], kh[jp][3], a);
            }
            #pragma unroll
            for (int jp = 0; jp < 4; ++jp) {
                mma16816(s_[2*jp],     qh[f], kh[jp]);
                mma16816(s_[2*jp + 1], qh[f], kh[jp] + 2);
            }
        }

        // ---- causal mask (diagonal tile only) ----
        if (jt == qt) {
            const int qrow  = qt * 64 + wq + (lane >> 2);
            const int kcol0 = jt * 64 + (lane & 3) * 2;
            #pragma unroll
            for (int j = 0; j < 8; ++j) {
                int c0 = kcol0 + j * 8, c1 = c0 + 1;
                if (c0 > qrow)     s_[j][0] = -1e30f;
                if (c1 > qrow)     s_[j][1] = -1e30f;
                if (c0 > qrow + 8) s_[j][2] = -1e30f;
                if (c1 > qrow + 8) s_[j][3] = -1e30f;
            }
        }

        // ---- max-free softmax (MUFU.EX2) ----
        #pragma unroll
        for (int j = 0; j < 8; ++j) {
            s_[j][0] = ex2(s_[j][0]);
            s_[j][1] = ex2(s_[j][1]);
            s_[j][2] = ex2(s_[j][2]);
            s_[j][3] = ex2(s_[j][3]);
            rs0 += s_[j][0] + s_[j][1];
            rs1 += s_[j][2] + s_[j][3];
        }

        // ---- O += P V (1-pass, P rounded to fp16) ----
        const uint32_t vb = kb + KVB + vrow;
        #pragma unroll
        for (int f = 0; f < 4; ++f) {
            uint32_t ph[4];
            #pragma unroll
            for (int t = 0; t < 2; ++t) {
                ph[2*t]   = packh2(s_[2*f + t][0], s_[2*f + t][1]);
                ph[2*t+1] = packh2(s_[2*f + t][2], s_[2*f + t][3]);
            }
            const uint32_t va = vb + f * 16 * APITCH;
            uint32_t vh[4][4];
            #pragma unroll
            for (int dj = 0; dj < 4; ++dj)
                ldsm4t(vh[dj][0], vh[dj][1], vh[dj][2], vh[dj][3], va + dj * 32);
            #pragma unroll
            for (int dj = 0; dj < 4; ++dj) {
                mma16816(O[2*dj],     ph, vh[dj]);
                mma16816(O[2*dj + 1], ph, vh[dj] + 2);
            }
        }
        __syncthreads();
    }

    // ---- finalize ----
    rs0 += __shfl_xor_sync(0xffffffffu, rs0, 1);
    rs0 += __shfl_xor_sync(0xffffffffu, rs0, 2);
    rs1 += __shfl_xor_sync(0xffffffffu, rs1, 1);
    rs1 += __shfl_xor_sync(0xffffffffu, rs1, 2);
    const float inv0 = 1.0f / rs0, inv1 = 1.0f / rs1;

    const int r    = lane >> 2;
    const int dcol = (lane & 3) * 2;
    const int row0 = qt * 64 + wq + r;
    const size_t base0 = ((size_t)b * SS + row0) * DOUT + h * 64;
    const size_t base1 = base0 + (size_t)8 * DOUT;
    #pragma unroll
    for (int dj = 0; dj < 8; ++dj) {
        int d = dj * 8 + dcol;
        *(uint32_t*)&g_cxh[base0 + d] = packh2(O[dj][0] * inv0, O[dj][1] * inv0);
        *(uint32_t*)&g_cxh[base1 + d] = packh2(O[dj][2] * inv1, O[dj][3] * inv1);
    }
}

// ---------------------------------------------------------------------------
extern "C" void kernel_launch(void* const* d_in, const int* in_sizes, int n_in,
                              void* d_out, int out_size)
{
    const float* x  = (const float*)d_in[0];
    const float* Wq = (const float*)d_in[1];
    const float* Wk = (const float*)d_in[2];
    const float* Wv = (const float*)d_in[3];
    const float* Wo = (const float*)d_in[4];
    const float* bo = (const float*)d_in[5];
    float* out = (float*)d_out;

    cudaFuncSetAttribute(mma_gemm<0>, cudaFuncAttributeMaxDynamicSharedMemorySize, GSMEM);
    cudaFuncSetAttribute(mma_gemm<1>, cudaFuncAttributeMaxDynamicSharedMemorySize, GSMEM);
    cudaFuncSetAttribute(attn_mma_kernel, cudaFuncAttributeMaxDynamicSharedMemorySize, ATTN_SMEM);

    conv_all_kernel<<<12288, 256>>>(x, Wq, Wk, Wv, Wo);
    mma_gemm<0><<<dim3(64, 8, 3), 256, GSMEM>>>(nullptr, nullptr);
    attn_mma_kernel<<<dim3(32, HH, BB), 128, ATTN_SMEM>>>();
    mma_gemm<1><<<dim3(64, 8), 256, GSMEM>>>(bo, out);
}